// round 3
// baseline (speedup 1.0000x reference)
#include <cuda_runtime.h>
#include <cuda_bf16.h>
#include <cstdint>

#define NN 200000
#define NE 4000000
#define RR 4
#define DD 64
#define NRSEG (NN*RR)
#define GG 64
#define CC 10
#define SCAN_BLOCKS ((NRSEG + 1023) / 1024)

// ---------------- device scratch (no allocations allowed) ----------------
static __device__ __align__(16) int   g_cnt[NRSEG];
static __device__ __align__(16) int   g_off[NRSEG];
static __device__ __align__(16) int   g_cursor[NRSEG];
static __device__ __align__(16) int   g_bsum[1024];
static __device__ __align__(16) int   g_sorted[NE];
static __device__ __align__(16) int   g_goff[GG + 1];
static __device__ __align__(16) __nv_bfloat16 g_hA[NN * DD];
static __device__ __align__(16) __nv_bfloat16 g_hB[NN * DD];
static __device__ __align__(16) float g_pooled[GG * DD];

// ---------------- setup: counting sort of edges by (tgt*R + etype) -------
__global__ void k_zero_cnt() {
    int i = blockIdx.x * blockDim.x + threadIdx.x;
    if (i < NRSEG) g_cnt[i] = 0;
}

__global__ void k_hist(const int* __restrict__ tgt, const int* __restrict__ et) {
    int e = blockIdx.x * blockDim.x + threadIdx.x;
    if (e < NE) atomicAdd(&g_cnt[tgt[e] * RR + et[e]], 1);
}

__global__ void k_scan1() {
    __shared__ int sh[1024];
    int t = threadIdx.x;
    int i = blockIdx.x * 1024 + t;
    int v = (i < NRSEG) ? g_cnt[i] : 0;
    sh[t] = v;
    __syncthreads();
    for (int s = 1; s < 1024; s <<= 1) {
        int add = (t >= s) ? sh[t - s] : 0;
        __syncthreads();
        sh[t] += add;
        __syncthreads();
    }
    if (i < NRSEG) g_off[i] = sh[t] - v;          // exclusive
    if (t == 1023) g_bsum[blockIdx.x] = sh[1023]; // block total
}

__global__ void k_scan2() {
    __shared__ int sh[1024];
    int t = threadIdx.x;
    int v = (t < SCAN_BLOCKS) ? g_bsum[t] : 0;
    sh[t] = v;
    __syncthreads();
    for (int s = 1; s < 1024; s <<= 1) {
        int add = (t >= s) ? sh[t - s] : 0;
        __syncthreads();
        sh[t] += add;
        __syncthreads();
    }
    if (t < SCAN_BLOCKS) g_bsum[t] = sh[t] - v;   // exclusive
}

__global__ void k_scan3() {
    int i = blockIdx.x * blockDim.x + threadIdx.x;
    if (i < NRSEG) {
        int o = g_off[i] + g_bsum[i >> 10];
        g_off[i] = o;
        g_cursor[i] = o;
    }
}

__global__ void k_scatter(const int* __restrict__ srcarr, const int* __restrict__ tgt,
                          const int* __restrict__ et) {
    int e = blockIdx.x * blockDim.x + threadIdx.x;
    if (e < NE) {
        int s = tgt[e] * RR + et[e];
        int p = atomicAdd(&g_cursor[s], 1);
        g_sorted[p] = srcarr[e];
    }
}

// ---------------- node embedding init (fp32 compute -> bf16 store) --------
__global__ void k_h0(const int* __restrict__ xop, const int* __restrict__ xcat,
                     const float* __restrict__ opemb, const float* __restrict__ catemb) {
    int i = blockIdx.x * blockDim.x + threadIdx.x;
    if (i >= NN * 32) return;
    int n = i >> 5, j = i & 31;
    const float2* oe = (const float2*)opemb;
    const float2* ce = (const float2*)catemb;
    float2 a = oe[xop[n] * 32 + j];
    float2 b = ce[xcat[n] * 32 + j];
    ((__nv_bfloat162*)g_hA)[n * 32 + j] =
        __float22bfloat162_rn(make_float2(a.x + b.x, a.y + b.y));
}

// ---------------- fused layer: agg-into-smem + tensor-core GEMM -----------
// h_out = [M_0|M_1|M_2|M_3|h] @ [W_0..W_3|root] + b, M_r = per-relation mean.
// Block tile 128 nodes x 64 outputs, K = 5 chunks of 64.
// For chunk c<4, warp wp aggregates relation-c means of its 16 nodes straight
// into the As tile (fp32 accum, bf16 store). Chunk 4 stages h from global.
// Smem stride 72 elems (144 B == 16 mod 128) -> conflict-free ldmatrix.
#define ASTR 72
__global__ __launch_bounds__(256) void k_layer(int inB,
                                               const float* __restrict__ w,
                                               const float* __restrict__ root,
                                               const float* __restrict__ bias,
                                               int do_relu) {
    __shared__ __nv_bfloat16 As[128 * ASTR];
    __shared__ __nv_bfloat16 Bs[64 * ASTR];
    __shared__ float biass[64];

    const __nv_bfloat16* hin = inB ? g_hB : g_hA;
    __nv_bfloat16* hout = inB ? g_hA : g_hB;
    const __nv_bfloat162* h2 = (const __nv_bfloat162*)hin;

    int tid = threadIdx.x;
    int lane = tid & 31;
    int wp = tid >> 5;
    int nbase = blockIdx.x * 128;

    if (tid < 64) biass[tid] = bias[tid];

    float d[4][2][4];
#pragma unroll
    for (int t = 0; t < 4; ++t)
#pragma unroll
        for (int s = 0; s < 2; ++s)
#pragma unroll
            for (int i = 0; i < 4; ++i) d[t][s][i] = 0.f;

    uint32_t as_base = (uint32_t)__cvta_generic_to_shared(As);
    uint32_t bs_base = (uint32_t)__cvta_generic_to_shared(Bs);

    for (int c = 0; c < 5; ++c) {
        __syncthreads();
        // ---- stage B chunk [64 k x 64 e], fp32 -> bf16
        {
            const float* bsrc = (c < 4) ? (w + c * 4096) : root;
#pragma unroll
            for (int it = 0; it < 8; ++it) {
                int idx = it * 256 + tid;      // 0..2047, one float2 each
                int kk = idx >> 5;
                int e2 = idx & 31;
                float2 v = *(const float2*)(bsrc + kk * 64 + e2 * 2);
                *(__nv_bfloat162*)(Bs + kk * ASTR + e2 * 2) = __float22bfloat162_rn(v);
            }
        }
        if (c < 4) {
            // ---- aggregate relation c for this warp's 16 nodes into As
            // coalesced prefetch of off/cnt: lanes 0-15 -> off, 16-31 -> cnt
            int nl = nbase + wp * 16 + (lane & 15);
            int pre = 0;
            if (nl < NN) {
                int s = nl * RR + c;
                pre = (lane < 16) ? g_off[s] : g_cnt[s];
            }
#pragma unroll 1
            for (int i = 0; i < 16; ++i) {
                int gn = nbase + wp * 16 + i;
                int st = __shfl_sync(0xffffffffu, pre, i);
                int cv = __shfl_sync(0xffffffffu, pre, 16 + i);
                float ax = 0.f, ay = 0.f;
                if (gn < NN && cv > 0) {
                    int end = st + cv;
                    for (int base = st; base < end; base += 32) {
                        int m = end - base;
                        if (m > 32) m = 32;
                        int idx = (lane < m) ? g_sorted[base + lane] : 0;
                        int t = 0;
                        for (; t + 4 <= m; t += 4) {
                            int s0 = __shfl_sync(0xffffffffu, idx, t);
                            int s1 = __shfl_sync(0xffffffffu, idx, t + 1);
                            int s2 = __shfl_sync(0xffffffffu, idx, t + 2);
                            int s3 = __shfl_sync(0xffffffffu, idx, t + 3);
                            float2 v0 = __bfloat1622float2(h2[s0 * 32 + lane]);
                            float2 v1 = __bfloat1622float2(h2[s1 * 32 + lane]);
                            float2 v2 = __bfloat1622float2(h2[s2 * 32 + lane]);
                            float2 v3 = __bfloat1622float2(h2[s3 * 32 + lane]);
                            ax += v0.x + v1.x + v2.x + v3.x;
                            ay += v0.y + v1.y + v2.y + v3.y;
                        }
                        for (; t < m; ++t) {
                            int sn = __shfl_sync(0xffffffffu, idx, t);
                            float2 v = __bfloat1622float2(h2[sn * 32 + lane]);
                            ax += v.x;
                            ay += v.y;
                        }
                    }
                    float inv = 1.f / (float)cv;
                    ax *= inv;
                    ay *= inv;
                }
                *(__nv_bfloat162*)(As + (wp * 16 + i) * ASTR + lane * 2) =
                    __float22bfloat162_rn(make_float2(ax, ay));
            }
        } else {
            // ---- stage h rows [128 nodes x 64 k] from global
#pragma unroll
            for (int it = 0; it < 4; ++it) {
                int idx = it * 256 + tid;      // 0..1023, 8 bf16 each
                int node = idx & 127;
                int k8 = idx >> 7;             // 0..7
                int gn = nbase + node;
                uint2 lo = make_uint2(0u, 0u), hi = make_uint2(0u, 0u);
                if (gn < NN) {
                    uint4 v = *(const uint4*)(hin + gn * 64 + k8 * 8);
                    lo = make_uint2(v.x, v.y);
                    hi = make_uint2(v.z, v.w);
                }
                __nv_bfloat16* dst = As + node * ASTR + k8 * 8;
                *(uint2*)(dst) = lo;
                *(uint2*)(dst + 4) = hi;
            }
        }
        __syncthreads();
        // ---- 4 k-steps of 16 over this chunk
#pragma unroll
        for (int ks = 0; ks < 4; ++ks) {
            uint32_t a0, a1, a2, a3;
            uint32_t aaddr = as_base +
                ((wp * 16 + (lane & 15)) * ASTR + ks * 16 + ((lane >> 4) << 3)) * 2;
            asm volatile(
                "ldmatrix.sync.aligned.m8n8.x4.shared.b16 {%0,%1,%2,%3}, [%4];"
                : "=r"(a0), "=r"(a1), "=r"(a2), "=r"(a3) : "r"(aaddr));
#pragma unroll
            for (int t = 0; t < 4; ++t) {
                uint32_t b0, b1, b2, b3;
                uint32_t baddr = bs_base +
                    ((ks * 16 + (lane & 15)) * ASTR + t * 16 + ((lane >> 4) << 3)) * 2;
                asm volatile(
                    "ldmatrix.sync.aligned.m8n8.x4.trans.shared.b16 {%0,%1,%2,%3}, [%4];"
                    : "=r"(b0), "=r"(b1), "=r"(b2), "=r"(b3) : "r"(baddr));
                asm volatile(
                    "mma.sync.aligned.m16n8k16.row.col.f32.bf16.bf16.f32 "
                    "{%0,%1,%2,%3}, {%4,%5,%6,%7}, {%8,%9}, {%0,%1,%2,%3};"
                    : "+f"(d[t][0][0]), "+f"(d[t][0][1]), "+f"(d[t][0][2]), "+f"(d[t][0][3])
                    : "r"(a0), "r"(a1), "r"(a2), "r"(a3), "r"(b0), "r"(b1));
                asm volatile(
                    "mma.sync.aligned.m16n8k16.row.col.f32.bf16.bf16.f32 "
                    "{%0,%1,%2,%3}, {%4,%5,%6,%7}, {%8,%9}, {%0,%1,%2,%3};"
                    : "+f"(d[t][1][0]), "+f"(d[t][1][1]), "+f"(d[t][1][2]), "+f"(d[t][1][3])
                    : "r"(a0), "r"(a1), "r"(a2), "r"(a3), "r"(b2), "r"(b3));
            }
        }
    }

    // ---- epilogue: bias + relu, bf16 store
    int r0 = nbase + wp * 16 + (lane >> 2);
    int r1 = r0 + 8;
    __nv_bfloat162* hout2 = (__nv_bfloat162*)hout;
#pragma unroll
    for (int t = 0; t < 4; ++t) {
#pragma unroll
        for (int s = 0; s < 2; ++s) {
            int n0 = t * 16 + s * 8 + (lane & 3) * 2;
            float bx = biass[n0], by = biass[n0 + 1];
            float v0 = d[t][s][0] + bx, v1 = d[t][s][1] + by;
            float v2 = d[t][s][2] + bx, v3 = d[t][s][3] + by;
            if (do_relu) {
                v0 = fmaxf(v0, 0.f); v1 = fmaxf(v1, 0.f);
                v2 = fmaxf(v2, 0.f); v3 = fmaxf(v3, 0.f);
            }
            if (r0 < NN)
                hout2[r0 * 32 + n0 / 2] = __float22bfloat162_rn(make_float2(v0, v1));
            if (r1 < NN)
                hout2[r1 * 32 + n0 / 2] = __float22bfloat162_rn(make_float2(v2, v3));
        }
    }
}

// ---------------- pooling (batch sorted -> graph boundary offsets) --------
__global__ void k_goff(const int* __restrict__ batch) {
    int n = blockIdx.x * blockDim.x + threadIdx.x;
    if (n >= NN) return;
    int b = batch[n];
    if (n == 0) {
        for (int g = 0; g <= b; ++g) g_goff[g] = 0;
    } else {
        int bp = batch[n - 1];
        for (int g = bp + 1; g <= b; ++g) g_goff[g] = n;
    }
    if (n == NN - 1) {
        for (int g = b + 1; g <= GG; ++g) g_goff[g] = NN;
    }
}

__global__ void k_pool(int inB) {
    const __nv_bfloat16* h = inB ? g_hB : g_hA;
    int g = blockIdx.x;
    int st = g_goff[g], en = g_goff[g + 1];
    int d = threadIdx.x & 63;
    int y = threadIdx.x >> 6;
    float acc = 0.f;
    for (int n = st + y; n < en; n += 4) acc += __bfloat162float(h[n * DD + d]);
    __shared__ float red[4][64];
    red[y][d] = acc;
    __syncthreads();
    if (y == 0) {
        float s = red[0][d] + red[1][d] + red[2][d] + red[3][d];
        int c = en - st;
        g_pooled[g * DD + d] = s / (float)(c > 0 ? c : 1);
    }
}

// ---------------- MLP head + log_softmax (tiny) ----------------------------
__global__ void k_head(const float* __restrict__ fc1w, const float* __restrict__ fc1b,
                       const float* __restrict__ fc2w, const float* __restrict__ fc2b,
                       float* __restrict__ out) {
    __shared__ float w1s[DD * DD];
    __shared__ float w2s[DD * CC];
    __shared__ float b1s[DD];
    __shared__ float b2s[CC];
    int t = threadIdx.x; // 64 threads
    for (int i = t; i < DD * DD; i += 64) w1s[i] = fc1w[i];
    for (int i = t; i < DD * CC; i += 64) w2s[i] = fc2w[i];
    if (t < DD) b1s[t] = fc1b[t];
    if (t < CC) b2s[t] = fc2b[t];
    __syncthreads();
    int g = t;
    float p[DD];
#pragma unroll
    for (int d = 0; d < DD; ++d) p[d] = g_pooled[g * DD + d];
    float t1[DD];
    for (int e = 0; e < DD; ++e) {
        float a = b1s[e];
#pragma unroll
        for (int d = 0; d < DD; ++d) a += p[d] * w1s[d * DD + e];
        t1[e] = fmaxf(a, 0.f);
    }
    float lg[CC];
    for (int c = 0; c < CC; ++c) {
        float a = b2s[c];
#pragma unroll
        for (int e = 0; e < DD; ++e) a += t1[e] * w2s[e * CC + c];
        lg[c] = a;
    }
    float m = lg[0];
    for (int c = 1; c < CC; ++c) m = fmaxf(m, lg[c]);
    float s = 0.f;
    for (int c = 0; c < CC; ++c) s += expf(lg[c] - m);
    float ls = logf(s);
    for (int c = 0; c < CC; ++c) out[g * CC + c] = lg[c] - m - ls;
}

// ---------------- launch --------------------------------------------------
extern "C" void kernel_launch(void* const* d_in, const int* in_sizes, int n_in,
                              void* d_out, int out_size) {
    const int* x_op = (const int*)d_in[0];
    const int* x_cat = (const int*)d_in[1];
    const int* ei = (const int*)d_in[2];
    const int* etyp = (const int*)d_in[3];
    const int* batch = (const int*)d_in[4];
    const float* opemb = (const float*)d_in[5];
    const float* catemb = (const float*)d_in[6];
    const float* W[3] = {(const float*)d_in[7], (const float*)d_in[10], (const float*)d_in[13]};
    const float* Rt[3] = {(const float*)d_in[8], (const float*)d_in[11], (const float*)d_in[14]};
    const float* Bi[3] = {(const float*)d_in[9], (const float*)d_in[12], (const float*)d_in[15]};
    const float* fc1w = (const float*)d_in[16];
    const float* fc1b = (const float*)d_in[17];
    const float* fc2w = (const float*)d_in[18];
    const float* fc2b = (const float*)d_in[19];
    float* out = (float*)d_out;
    const int* src = ei;
    const int* tgt = ei + NE;

    // edge sort (reused by all 3 layers)
    k_zero_cnt<<<(NRSEG + 255) / 256, 256>>>();
    k_hist<<<(NE + 255) / 256, 256>>>(tgt, etyp);
    k_scan1<<<SCAN_BLOCKS, 1024>>>();
    k_scan2<<<1, 1024>>>();
    k_scan3<<<(NRSEG + 255) / 256, 256>>>();
    k_scatter<<<(NE + 255) / 256, 256>>>(src, tgt, etyp);

    k_h0<<<(NN * 32 + 255) / 256, 256>>>(x_op, x_cat, opemb, catemb);
    k_goff<<<(NN + 255) / 256, 256>>>(batch);

    // 3 fused RGCN layers, ping-pong hA/hB. l=0: A->B, l=1: B->A, l=2: A->B
    for (int l = 0; l < 3; ++l) {
        int inB = l & 1;
        k_layer<<<(NN + 127) / 128, 256>>>(inB, W[l], Rt[l], Bi[l], (l < 2) ? 1 : 0);
    }

    k_pool<<<GG, 256>>>(1); // final h is in g_hB
    k_head<<<1, 64>>>(fc1w, fc1b, fc2w, fc2b, out);
}

// round 4
// speedup vs baseline: 1.2296x; 1.2296x over previous
#include <cuda_runtime.h>
#include <cuda_bf16.h>
#include <cstdint>

#define NN 200000
#define NE 4000000
#define RR 4
#define DD 64
#define NRSEG (NN*RR)
#define GG 64
#define CC 10
#define SCAN_BLOCKS ((NRSEG + 1023) / 1024)

// ---------------- device scratch (no allocations allowed) ----------------
static __device__ __align__(16) int   g_cnt[NRSEG];
static __device__ __align__(16) int   g_off[NRSEG];
static __device__ __align__(16) int   g_cursor[NRSEG];
static __device__ __align__(16) int   g_bsum[1024];
static __device__ __align__(16) int   g_sorted[NE];
static __device__ __align__(16) int   g_goff[GG + 1];
static __device__ __align__(16) __nv_bfloat16 g_hA[NN * DD];
static __device__ __align__(16) __nv_bfloat16 g_hB[NN * DD];
static __device__ __align__(16) __nv_bfloat16 g_M[NN * RR * DD];
static __device__ __align__(16) float g_pooled[GG * DD];

// ---------------- setup: counting sort of edges by (tgt*R + etype) -------
__global__ void k_zero_cnt() {
    int i = blockIdx.x * blockDim.x + threadIdx.x;
    if (i < NRSEG) g_cnt[i] = 0;
}

__global__ void k_hist(const int* __restrict__ tgt, const int* __restrict__ et) {
    int e = blockIdx.x * blockDim.x + threadIdx.x;
    if (e < NE) atomicAdd(&g_cnt[tgt[e] * RR + et[e]], 1);
}

__global__ void k_scan1() {
    __shared__ int sh[1024];
    int t = threadIdx.x;
    int i = blockIdx.x * 1024 + t;
    int v = (i < NRSEG) ? g_cnt[i] : 0;
    sh[t] = v;
    __syncthreads();
    for (int s = 1; s < 1024; s <<= 1) {
        int add = (t >= s) ? sh[t - s] : 0;
        __syncthreads();
        sh[t] += add;
        __syncthreads();
    }
    if (i < NRSEG) g_off[i] = sh[t] - v;          // exclusive
    if (t == 1023) g_bsum[blockIdx.x] = sh[1023]; // block total
}

__global__ void k_scan2() {
    __shared__ int sh[1024];
    int t = threadIdx.x;
    int v = (t < SCAN_BLOCKS) ? g_bsum[t] : 0;
    sh[t] = v;
    __syncthreads();
    for (int s = 1; s < 1024; s <<= 1) {
        int add = (t >= s) ? sh[t - s] : 0;
        __syncthreads();
        sh[t] += add;
        __syncthreads();
    }
    if (t < SCAN_BLOCKS) g_bsum[t] = sh[t] - v;   // exclusive
}

__global__ void k_scan3() {
    int i = blockIdx.x * blockDim.x + threadIdx.x;
    if (i < NRSEG) {
        int o = g_off[i] + g_bsum[i >> 10];
        g_off[i] = o;
        g_cursor[i] = o;
    }
}

__global__ void k_scatter(const int* __restrict__ srcarr, const int* __restrict__ tgt,
                          const int* __restrict__ et) {
    int e = blockIdx.x * blockDim.x + threadIdx.x;
    if (e < NE) {
        int s = tgt[e] * RR + et[e];
        int p = atomicAdd(&g_cursor[s], 1);
        g_sorted[p] = srcarr[e];
    }
}

// ---------------- node embedding init (fp32 compute -> bf16 store) --------
__global__ void k_h0(const int* __restrict__ xop, const int* __restrict__ xcat,
                     const float* __restrict__ opemb, const float* __restrict__ catemb) {
    int i = blockIdx.x * blockDim.x + threadIdx.x;
    if (i >= NN * 32) return;
    int n = i >> 5, j = i & 31;
    const float2* oe = (const float2*)opemb;
    const float2* ce = (const float2*)catemb;
    float2 a = oe[xop[n] * 32 + j];
    float2 b = ce[xcat[n] * 32 + j];
    ((__nv_bfloat162*)g_hA)[n * 32 + j] =
        __float22bfloat162_rn(make_float2(a.x + b.x, a.y + b.y));
}

// ---------------- per-(node,relation) mean aggregation v2 -----------------
// Warp = 1 node. Four 8-lane groups; group g owns relation g entirely.
// Lane (g,q): q-th 16B chunk (8 bf16 dims) of each gathered row.
// One coalesced idx load serves all 4 relations' first 8 edges; each edge
// costs one LDG.128 per lane; loop trips = max_r cnt_r (not sum).
__global__ __launch_bounds__(256) void k_agg(int inB) {
    int gw = (blockIdx.x * blockDim.x + threadIdx.x) >> 5;
    int lane = threadIdx.x & 31;
    if (gw >= NN) return;
    int q = lane & 7;        // 16B chunk within row
    int g = lane >> 3;       // relation group
    const __nv_bfloat16* hin = inB ? g_hB : g_hA;

    // prologue: lanes 0-3 off, lanes 4-7 cnt
    int pre = 0;
    if (lane < 8) pre = (lane < 4) ? g_off[gw * RR + lane] : g_cnt[gw * RR + lane - 4];
    int off_g = __shfl_sync(0xffffffffu, pre, g);
    int cnt_g = __shfl_sync(0xffffffffu, pre, 4 + g);

    float acc[8];
#pragma unroll
    for (int j = 0; j < 8; ++j) acc[j] = 0.f;

    for (int base = 0; ; base += 8) {
        int rem = cnt_g - base;              // group-uniform
        int m = rem < 8 ? rem : 8;           // edges this pass for my group
        // warp max of m across the 4 groups
        int mm = m;
        mm = max(mm, __shfl_xor_sync(0xffffffffu, mm, 8));
        mm = max(mm, __shfl_xor_sync(0xffffffffu, mm, 16));
        if (mm <= 0) break;
        int idx = (q < rem) ? g_sorted[off_g + base + q] : 0;
#pragma unroll 2
        for (int t = 0; t < mm; ++t) {
            int sn = __shfl_sync(0xffffffffu, idx, (lane & 24) + t);
            if (t < m) {
                uint4 v = *(const uint4*)(hin + sn * 64 + q * 8);
                const __nv_bfloat162* p = (const __nv_bfloat162*)&v;
                float2 f0 = __bfloat1622float2(p[0]);
                float2 f1 = __bfloat1622float2(p[1]);
                float2 f2 = __bfloat1622float2(p[2]);
                float2 f3 = __bfloat1622float2(p[3]);
                acc[0] += f0.x; acc[1] += f0.y;
                acc[2] += f1.x; acc[3] += f1.y;
                acc[4] += f2.x; acc[5] += f2.y;
                acc[6] += f3.x; acc[7] += f3.y;
            }
        }
        if (mm < 8) break;
    }

    float inv = (cnt_g > 0) ? (1.f / (float)cnt_g) : 0.f;
    __nv_bfloat162 o[4];
#pragma unroll
    for (int j = 0; j < 4; ++j)
        o[j] = __float22bfloat162_rn(make_float2(acc[2 * j] * inv, acc[2 * j + 1] * inv));
    *(uint4*)(g_M + (gw * RR + g) * 64 + q * 8) = *(const uint4*)o;
}

// ---------------- tensor-core GEMM: h_out = [M | h] @ [W | root] + b -------
// block tile: 128 nodes (M) x 64 outputs (N), K = 5 chunks of 64.
// bf16 mma.sync m16n8k16, fp32 accumulate. 8 warps, warp w -> rows [16w,16w+16).
#define ASTR 72
__global__ __launch_bounds__(256) void k_gemm(int inB,
                                              const float* __restrict__ w,
                                              const float* __restrict__ root,
                                              const float* __restrict__ bias,
                                              int do_relu) {
    __shared__ __nv_bfloat16 As[128 * ASTR];
    __shared__ __nv_bfloat16 Bs[64 * ASTR];
    __shared__ float biass[64];

    const __nv_bfloat16* hin = inB ? g_hB : g_hA;
    __nv_bfloat16* hout = inB ? g_hA : g_hB;

    int tid = threadIdx.x;
    int lane = tid & 31;
    int wp = tid >> 5;
    int nbase = blockIdx.x * 128;

    if (tid < 64) biass[tid] = bias[tid];

    float d[4][2][4];
#pragma unroll
    for (int t = 0; t < 4; ++t)
#pragma unroll
        for (int s = 0; s < 2; ++s)
#pragma unroll
            for (int i = 0; i < 4; ++i) d[t][s][i] = 0.f;

    uint32_t as_base = (uint32_t)__cvta_generic_to_shared(As);
    uint32_t bs_base = (uint32_t)__cvta_generic_to_shared(Bs);

    for (int c = 0; c < 5; ++c) {
        __syncthreads();
        // ---- stage B chunk [64 k x 64 e], fp32 -> bf16
        {
            const float* bsrc = (c < 4) ? (w + c * 4096) : root;
#pragma unroll
            for (int it = 0; it < 8; ++it) {
                int idx = it * 256 + tid;
                int kk = idx >> 5;
                int e2 = idx & 31;
                float2 v = *(const float2*)(bsrc + kk * 64 + e2 * 2);
                *(__nv_bfloat162*)(Bs + kk * ASTR + e2 * 2) = __float22bfloat162_rn(v);
            }
        }
        // ---- stage A chunk [128 nodes x 64 k] bf16 (M for c<4, h for c==4)
        {
#pragma unroll
            for (int it = 0; it < 4; ++it) {
                int idx = it * 256 + tid;
                int node = idx & 127;
                int k8 = idx >> 7;
                int gn = nbase + node;
                uint2 lo = make_uint2(0u, 0u), hi = make_uint2(0u, 0u);
                if (gn < NN) {
                    const uint4* srcp = (c < 4)
                        ? (const uint4*)(g_M + gn * 256 + c * 64 + k8 * 8)
                        : (const uint4*)(hin + gn * 64 + k8 * 8);
                    uint4 v = *srcp;
                    lo = make_uint2(v.x, v.y);
                    hi = make_uint2(v.z, v.w);
                }
                __nv_bfloat16* dst = As + node * ASTR + k8 * 8;
                *(uint2*)(dst) = lo;
                *(uint2*)(dst + 4) = hi;
            }
        }
        __syncthreads();
#pragma unroll
        for (int ks = 0; ks < 4; ++ks) {
            uint32_t a0, a1, a2, a3;
            uint32_t aaddr = as_base +
                ((wp * 16 + (lane & 15)) * ASTR + ks * 16 + ((lane >> 4) << 3)) * 2;
            asm volatile(
                "ldmatrix.sync.aligned.m8n8.x4.shared.b16 {%0,%1,%2,%3}, [%4];"
                : "=r"(a0), "=r"(a1), "=r"(a2), "=r"(a3) : "r"(aaddr));
#pragma unroll
            for (int t = 0; t < 4; ++t) {
                uint32_t b0, b1, b2, b3;
                uint32_t baddr = bs_base +
                    ((ks * 16 + (lane & 15)) * ASTR + t * 16 + ((lane >> 4) << 3)) * 2;
                asm volatile(
                    "ldmatrix.sync.aligned.m8n8.x4.trans.shared.b16 {%0,%1,%2,%3}, [%4];"
                    : "=r"(b0), "=r"(b1), "=r"(b2), "=r"(b3) : "r"(baddr));
                asm volatile(
                    "mma.sync.aligned.m16n8k16.row.col.f32.bf16.bf16.f32 "
                    "{%0,%1,%2,%3}, {%4,%5,%6,%7}, {%8,%9}, {%0,%1,%2,%3};"
                    : "+f"(d[t][0][0]), "+f"(d[t][0][1]), "+f"(d[t][0][2]), "+f"(d[t][0][3])
                    : "r"(a0), "r"(a1), "r"(a2), "r"(a3), "r"(b0), "r"(b1));
                asm volatile(
                    "mma.sync.aligned.m16n8k16.row.col.f32.bf16.bf16.f32 "
                    "{%0,%1,%2,%3}, {%4,%5,%6,%7}, {%8,%9}, {%0,%1,%2,%3};"
                    : "+f"(d[t][1][0]), "+f"(d[t][1][1]), "+f"(d[t][1][2]), "+f"(d[t][1][3])
                    : "r"(a0), "r"(a1), "r"(a2), "r"(a3), "r"(b2), "r"(b3));
            }
        }
    }

    // ---- epilogue: bias + relu, bf16 store
    int r0 = nbase + wp * 16 + (lane >> 2);
    int r1 = r0 + 8;
    __nv_bfloat162* hout2 = (__nv_bfloat162*)hout;
#pragma unroll
    for (int t = 0; t < 4; ++t) {
#pragma unroll
        for (int s = 0; s < 2; ++s) {
            int n0 = t * 16 + s * 8 + (lane & 3) * 2;
            float bx = biass[n0], by = biass[n0 + 1];
            float v0 = d[t][s][0] + bx, v1 = d[t][s][1] + by;
            float v2 = d[t][s][2] + bx, v3 = d[t][s][3] + by;
            if (do_relu) {
                v0 = fmaxf(v0, 0.f); v1 = fmaxf(v1, 0.f);
                v2 = fmaxf(v2, 0.f); v3 = fmaxf(v3, 0.f);
            }
            if (r0 < NN)
                hout2[r0 * 32 + n0 / 2] = __float22bfloat162_rn(make_float2(v0, v1));
            if (r1 < NN)
                hout2[r1 * 32 + n0 / 2] = __float22bfloat162_rn(make_float2(v2, v3));
        }
    }
}

// ---------------- pooling (batch sorted -> graph boundary offsets) --------
__global__ void k_goff(const int* __restrict__ batch) {
    int n = blockIdx.x * blockDim.x + threadIdx.x;
    if (n >= NN) return;
    int b = batch[n];
    if (n == 0) {
        for (int g = 0; g <= b; ++g) g_goff[g] = 0;
    } else {
        int bp = batch[n - 1];
        for (int g = bp + 1; g <= b; ++g) g_goff[g] = n;
    }
    if (n == NN - 1) {
        for (int g = b + 1; g <= GG; ++g) g_goff[g] = NN;
    }
}

__global__ void k_pool(int inB) {
    const __nv_bfloat16* h = inB ? g_hB : g_hA;
    int g = blockIdx.x;
    int st = g_goff[g], en = g_goff[g + 1];
    int d = threadIdx.x & 63;
    int y = threadIdx.x >> 6;
    float acc = 0.f;
    for (int n = st + y; n < en; n += 4) acc += __bfloat162float(h[n * DD + d]);
    __shared__ float red[4][64];
    red[y][d] = acc;
    __syncthreads();
    if (y == 0) {
        float s = red[0][d] + red[1][d] + red[2][d] + red[3][d];
        int c = en - st;
        g_pooled[g * DD + d] = s / (float)(c > 0 ? c : 1);
    }
}

// ---------------- MLP head + log_softmax (tiny) ----------------------------
__global__ void k_head(const float* __restrict__ fc1w, const float* __restrict__ fc1b,
                       const float* __restrict__ fc2w, const float* __restrict__ fc2b,
                       float* __restrict__ out) {
    __shared__ float w1s[DD * DD];
    __shared__ float w2s[DD * CC];
    __shared__ float b1s[DD];
    __shared__ float b2s[CC];
    int t = threadIdx.x; // 64 threads
    for (int i = t; i < DD * DD; i += 64) w1s[i] = fc1w[i];
    for (int i = t; i < DD * CC; i += 64) w2s[i] = fc2w[i];
    if (t < DD) b1s[t] = fc1b[t];
    if (t < CC) b2s[t] = fc2b[t];
    __syncthreads();
    int g = t;
    float p[DD];
#pragma unroll
    for (int d = 0; d < DD; ++d) p[d] = g_pooled[g * DD + d];
    float t1[DD];
    for (int e = 0; e < DD; ++e) {
        float a = b1s[e];
#pragma unroll
        for (int d = 0; d < DD; ++d) a += p[d] * w1s[d * DD + e];
        t1[e] = fmaxf(a, 0.f);
    }
    float lg[CC];
    for (int c = 0; c < CC; ++c) {
        float a = b2s[c];
#pragma unroll
        for (int e = 0; e < DD; ++e) a += t1[e] * w2s[e * CC + c];
        lg[c] = a;
    }
    float m = lg[0];
    for (int c = 1; c < CC; ++c) m = fmaxf(m, lg[c]);
    float s = 0.f;
    for (int c = 0; c < CC; ++c) s += expf(lg[c] - m);
    float ls = logf(s);
    for (int c = 0; c < CC; ++c) out[g * CC + c] = lg[c] - m - ls;
}

// ---------------- launch --------------------------------------------------
extern "C" void kernel_launch(void* const* d_in, const int* in_sizes, int n_in,
                              void* d_out, int out_size) {
    const int* x_op = (const int*)d_in[0];
    const int* x_cat = (const int*)d_in[1];
    const int* ei = (const int*)d_in[2];
    const int* etyp = (const int*)d_in[3];
    const int* batch = (const int*)d_in[4];
    const float* opemb = (const float*)d_in[5];
    const float* catemb = (const float*)d_in[6];
    const float* W[3] = {(const float*)d_in[7], (const float*)d_in[10], (const float*)d_in[13]};
    const float* Rt[3] = {(const float*)d_in[8], (const float*)d_in[11], (const float*)d_in[14]};
    const float* Bi[3] = {(const float*)d_in[9], (const float*)d_in[12], (const float*)d_in[15]};
    const float* fc1w = (const float*)d_in[16];
    const float* fc1b = (const float*)d_in[17];
    const float* fc2w = (const float*)d_in[18];
    const float* fc2b = (const float*)d_in[19];
    float* out = (float*)d_out;
    const int* src = ei;
    const int* tgt = ei + NE;

    // edge sort (reused by all 3 layers)
    k_zero_cnt<<<(NRSEG + 255) / 256, 256>>>();
    k_hist<<<(NE + 255) / 256, 256>>>(tgt, etyp);
    k_scan1<<<SCAN_BLOCKS, 1024>>>();
    k_scan2<<<1, 1024>>>();
    k_scan3<<<(NRSEG + 255) / 256, 256>>>();
    k_scatter<<<(NE + 255) / 256, 256>>>(src, tgt, etyp);

    k_h0<<<(NN * 32 + 255) / 256, 256>>>(x_op, x_cat, opemb, catemb);
    k_goff<<<(NN + 255) / 256, 256>>>(batch);

    // 3 RGCN layers, ping-pong hA/hB. l=0: A->B, l=1: B->A, l=2: A->B
    for (int l = 0; l < 3; ++l) {
        int inB = l & 1;
        k_agg<<<(NN * 32 + 255) / 256, 256>>>(inB);
        k_gemm<<<(NN + 127) / 128, 256>>>(inB, W[l], Rt[l], Bi[l], (l < 2) ? 1 : 0);
    }

    k_pool<<<GG, 256>>>(1); // final h is in g_hB
    k_head<<<1, 64>>>(fc1w, fc1b, fc2w, fc2b, out);
}